// round 12
// baseline (speedup 1.0000x reference)
#include <cuda_runtime.h>
#include <cuda_fp16.h>
#include <cstdint>

// ---------------- problem constants ----------------
#define NN 10000            // nodes
#define BB 64               // batch
#define DD 66               // input feature dim
#define OO 64               // output dim
#define UU 320              // 5 * OO
#define FF 4096             // BB * OO  (spmm feature width, node-major)
#define EMAX 200000
#define NFSZ ((size_t)NN * FF)

#define KP 80               // padded K (5 k-tiles of 16)
#define SA 88               // As row stride in halfs (conflict-free frag loads)
#define SU 320              // Ws row stride in halfs
#define NPB 8               // nodes per gemm block
#define GEMM_SMEM (KP * SU * 2 + BB * SA * 2)   // 51200 + 11264 = 62464 B

// ---------------- device scratch (static: no allocs allowed) ----------------
__device__ float  g_P[NFSZ];            // P fp32
__device__ __half g_H[4][NFSZ];         // Y1..Y4 fp16; T0 overwrites Y1, T1 overwrites Y3
__device__ int    g_rp[2][NN + 1];
__device__ int    g_cnt[2][NN];         // zero at load; re-zeroed each replay by k_spmm_cheb
__device__ int    g_cur[2][NN];
__device__ int    g_ecols[2][EMAX];
__device__ float  g_evals[2][EMAX];

// ---------------- CSR build ----------------
__global__ void k_hist2(const int* __restrict__ rows0, const int* __restrict__ rows1,
                        int E) {
    int e = blockIdx.x * blockDim.x + threadIdx.x;
    int sup = blockIdx.y;
    const int* rows = sup ? rows1 : rows0;
    if (e < E) atomicAdd(&g_cnt[sup][rows[e]], 1);
}

__global__ void k_scan() {
    __shared__ int ssum[1024];
    int sup = blockIdx.x;
    const int* cnt = g_cnt[sup];
    int* rp  = g_rp[sup];
    int* cur = g_cur[sup];
    int t = threadIdx.x;
    int base = t * 10;
    int local[10];
    int sum = 0;
#pragma unroll
    for (int k = 0; k < 10; k++) {
        int i = base + k;
        int v = (i < NN) ? cnt[i] : 0;
        local[k] = sum;
        sum += v;
    }
    ssum[t] = sum;
    __syncthreads();
    for (int off = 1; off < 1024; off <<= 1) {
        int v = (t >= off) ? ssum[t - off] : 0;
        __syncthreads();
        ssum[t] += v;
        __syncthreads();
    }
    int prev = (t > 0) ? ssum[t - 1] : 0;
#pragma unroll
    for (int k = 0; k < 10; k++) {
        int i = base + k;
        if (i < NN) {
            int v = prev + local[k];
            rp[i]  = v;
            cur[i] = v;
        }
    }
    if (t == 1023) rp[NN] = ssum[1023];
}

__global__ void k_fill2(const int* __restrict__ rows0, const int* __restrict__ cols0,
                        const float* __restrict__ vals0,
                        const int* __restrict__ rows1, const int* __restrict__ cols1,
                        const float* __restrict__ vals1, int E) {
    int e = blockIdx.x * blockDim.x + threadIdx.x;
    int sup = blockIdx.y;
    const int*   rows = sup ? rows1 : rows0;
    const int*   cols = sup ? cols1 : cols0;
    const float* vals = sup ? vals1 : vals0;
    if (e < E) {
        int r = rows[e];
        int pos = atomicAdd(&g_cur[sup][r], 1);
        g_ecols[sup][pos] = cols[e];
        g_evals[sup][pos] = vals[e];
    }
}

// ---------------- tensor-core GEMM0 --------------------------------------
// P = x0(W0-W2-W4)+bias (fp32), Ym = x0 Wm (fp16), via mma.sync m16n8k16.
__device__ __forceinline__ void mma16816(float& c0, float& c1, float& c2, float& c3,
                                         uint32_t a0, uint32_t a1, uint32_t a2,
                                         uint32_t a3, uint32_t b0, uint32_t b1) {
    asm volatile(
        "mma.sync.aligned.m16n8k16.row.col.f32.f16.f16.f32 "
        "{%0,%1,%2,%3}, {%4,%5,%6,%7}, {%8,%9}, {%0,%1,%2,%3};\n"
        : "+f"(c0), "+f"(c1), "+f"(c2), "+f"(c3)
        : "r"(a0), "r"(a1), "r"(a2), "r"(a3), "r"(b0), "r"(b1));
}

__global__ void __launch_bounds__(256, 2)
k_gemm_tc(const float* __restrict__ x, const float* __restrict__ W,
          const float* __restrict__ bias) {
    extern __shared__ char smem[];
    __half* Ws = (__half*)smem;                    // [KP][SU]  folded weights fp16
    __half* As = (__half*)(smem + KP * SU * 2);    // [BB][SA]  one node fp16
    const uint32_t* As32 = (const uint32_t*)As;

    int tid  = threadIdx.x;
    int w    = tid >> 5;
    int lane = tid & 31;
    int qr   = lane >> 2;      // t/4
    int qc   = lane & 3;       // t%4

    // ---- stage folded weights ----
    for (int idx = tid; idx < KP * UU; idx += 256) {
        int d = idx / UU;
        int u = idx - d * UU;
        float v;
        if (d >= DD) v = 0.f;
        else if (u < 64)
            v = __ldg(&W[d * 320 + u]) - __ldg(&W[d * 320 + 128 + u])
              - __ldg(&W[d * 320 + 256 + u]);
        else
            v = __ldg(&W[d * 320 + u]);
        Ws[d * SU + u] = __float2half_rn(v);
    }
    __syncthreads();

    // ---- B fragments into registers (node-invariant) ----
    uint32_t Breg[5][5][2];
#pragma unroll
    for (int j = 0; j < 5; j++) {
        int u = j * 64 + w * 8 + qr;
#pragma unroll
        for (int kt = 0; kt < 5; kt++) {
            int k0 = kt * 16 + qc * 2;
            __half2 p0 = __halves2half2(Ws[k0 * SU + u], Ws[(k0 + 1) * SU + u]);
            __half2 p1 = __halves2half2(Ws[(k0 + 8) * SU + u], Ws[(k0 + 9) * SU + u]);
            Breg[j][kt][0] = *(uint32_t*)&p0;
            Breg[j][kt][1] = *(uint32_t*)&p1;
        }
    }

    int oC = w * 8 + qc * 2;
    float bias0 = __ldg(&bias[oC]);
    float bias1 = __ldg(&bias[oC + 1]);

    for (int it = 0; it < NPB; it++) {
        int n = blockIdx.x * NPB + it;

        __syncthreads();
        for (int idx = tid; idx < BB * (KP / 2); idx += 256) {
            int b  = idx / (KP / 2);
            int d2 = idx - b * (KP / 2);
            int d  = d2 * 2;
            size_t gbase = (size_t)b * ((size_t)NN * DD) + (size_t)n * DD;
            float v0 = (d     < DD) ? __ldg(&x[gbase + d])     : 0.f;
            float v1 = (d + 1 < DD) ? __ldg(&x[gbase + d + 1]) : 0.f;
            ((__half2*)As)[b * (SA / 2) + d2] = __floats2half2_rn(v0, v1);
        }
        __syncthreads();

#pragma unroll
        for (int m = 0; m < 4; m++) {
            int r = m * 16 + qr;
            uint32_t a[5][4];
#pragma unroll
            for (int kt = 0; kt < 5; kt++) {
                a[kt][0] = As32[r * (SA / 2) + kt * 8 + qc];
                a[kt][1] = As32[(r + 8) * (SA / 2) + kt * 8 + qc];
                a[kt][2] = As32[r * (SA / 2) + kt * 8 + qc + 4];
                a[kt][3] = As32[(r + 8) * (SA / 2) + kt * 8 + qc + 4];
            }
#pragma unroll
            for (int j = 0; j < 5; j++) {
                float c0 = 0.f, c1 = 0.f, c2 = 0.f, c3 = 0.f;
#pragma unroll
                for (int kt = 0; kt < 5; kt++)
                    mma16816(c0, c1, c2, c3,
                             a[kt][0], a[kt][1], a[kt][2], a[kt][3],
                             Breg[j][kt][0], Breg[j][kt][1]);

                int bLo = m * 16 + qr;
                int bHi = bLo + 8;
                if (j == 0) {
                    float* dst = g_P + (size_t)n * FF;
                    *(float2*)&dst[bLo * 64 + oC] = make_float2(c0 + bias0, c1 + bias1);
                    *(float2*)&dst[bHi * 64 + oC] = make_float2(c2 + bias0, c3 + bias1);
                } else {
                    __half* dst = g_H[j - 1] + (size_t)n * FF;
                    __half2 hlo = __floats2half2_rn(c0, c1);
                    __half2 hhi = __floats2half2_rn(c2, c3);
                    *(__half2*)&dst[bLo * 64 + oC] = hlo;
                    *(__half2*)&dst[bHi * 64 + oC] = hhi;
                }
            }
        }
    }
}

// ---------------- SpMM gather core ----------------------------------------
__device__ __forceinline__ void gather_acc(int sup, const uint4* __restrict__ src,
                                           int r, int fq, float* acc) {
    const int*   rp   = g_rp[sup];
    const int*   cols = g_ecols[sup];
    const float* vals = g_evals[sup];
    int s = __ldg(&rp[r]);
    int e = __ldg(&rp[r + 1]);
    for (int i = s; i < e; i += 8) {
        int   cc[8];
        float vv[8];
#pragma unroll
        for (int j = 0; j < 8; j++) {
            int idx = i + j;
            bool ok = idx < e;
            cc[j] = ok ? __ldg(&cols[idx]) : 0;
            vv[j] = ok ? __ldg(&vals[idx]) : 0.f;
        }
#pragma unroll
        for (int j = 0; j < 8; j++) {
            uint4 q = __ldg(&src[(size_t)cc[j] * 512 + fq]);
            const __half2* hp = (const __half2*)&q;
            float2 f0v = __half22float2(hp[0]);
            float2 f1v = __half22float2(hp[1]);
            float2 f2v = __half22float2(hp[2]);
            float2 f3v = __half22float2(hp[3]);
            float v = vv[j];
            acc[0] = fmaf(v, f0v.x, acc[0]); acc[1] = fmaf(v, f0v.y, acc[1]);
            acc[2] = fmaf(v, f1v.x, acc[2]); acc[3] = fmaf(v, f1v.y, acc[3]);
            acc[4] = fmaf(v, f2v.x, acc[4]); acc[5] = fmaf(v, f2v.y, acc[5]);
            acc[6] = fmaf(v, f3v.x, acc[6]); acc[7] = fmaf(v, f3v.y, acc[7]);
        }
    }
}

// ---------------- Chebyshev SpMM: T = aux + 2*A*src (fp16, in-place) -------
// doZero: first instance also re-zeros g_cnt for the next graph replay.
__global__ void __launch_bounds__(128)
k_spmm_cheb(int sup, int srcIdx, int auxIdx, int doZero) {
    int r  = blockIdx.x;
    int fq = blockIdx.y * 128 + threadIdx.x;     // uint4 index within row (512/row)

    if (doZero && blockIdx.y == 0) {
        int gi = r * 128 + threadIdx.x;
        if (gi < 2 * NN) ((int*)g_cnt)[gi] = 0;
    }

    const uint4* src = (const uint4*)(g_H[srcIdx]);
    float acc[8] = {0.f, 0.f, 0.f, 0.f, 0.f, 0.f, 0.f, 0.f};
    gather_acc(sup, src, r, fq, acc);

    uint4* aux = (uint4*)(g_H[auxIdx]);
    uint4 qa = __ldg((const uint4*)&aux[(size_t)r * 512 + fq]);
    const __half2* hp = (const __half2*)&qa;
    float2 b0 = __half22float2(hp[0]);
    float2 b1 = __half22float2(hp[1]);
    float2 b2 = __half22float2(hp[2]);
    float2 b3 = __half22float2(hp[3]);
    __half2 h[4];
    h[0] = __floats2half2_rn(b0.x + 2.f * acc[0], b0.y + 2.f * acc[1]);
    h[1] = __floats2half2_rn(b1.x + 2.f * acc[2], b1.y + 2.f * acc[3]);
    h[2] = __floats2half2_rn(b2.x + 2.f * acc[4], b2.y + 2.f * acc[5]);
    h[3] = __floats2half2_rn(b3.x + 2.f * acc[6], b3.y + 2.f * acc[7]);
    aux[(size_t)r * 512 + fq] = *(uint4*)h;
}

// ---------------- Final fused dual-gather: out = P + A0*T0 + A1*T1 ---------
// Writes d_out transposed to [B, N*O].
__global__ void __launch_bounds__(128)
k_final(float* __restrict__ dout) {
    int r  = blockIdx.x;
    int fq = blockIdx.y * 128 + threadIdx.x;     // uint4 idx (8 feats per thread)

    float acc[8] = {0.f, 0.f, 0.f, 0.f, 0.f, 0.f, 0.f, 0.f};
    gather_acc(0, (const uint4*)(g_H[0]), r, fq, acc);   // A0 * T0
    gather_acc(1, (const uint4*)(g_H[2]), r, fq, acc);   // A1 * T1

    const float4* P4 = (const float4*)g_P;
    float4 p0 = __ldg(&P4[(size_t)r * 1024 + fq * 2]);
    float4 p1 = __ldg(&P4[(size_t)r * 1024 + fq * 2 + 1]);
    float4 r0 = make_float4(p0.x + acc[0], p0.y + acc[1], p0.z + acc[2], p0.w + acc[3]);
    float4 r1 = make_float4(p1.x + acc[4], p1.y + acc[5], p1.z + acc[6], p1.w + acc[7]);

    int f0 = fq * 8;
    int b  = f0 >> 6;
    int o  = f0 & 63;
    float4* od = (float4*)dout;
    size_t base = (size_t)b * ((size_t)NN * 16) + (size_t)r * 16 + (o >> 2);
    od[base]     = r0;
    od[base + 1] = r1;
}

// ---------------- launch ----------------
extern "C" void kernel_launch(void* const* d_in, const int* in_sizes, int n_in,
                              void* d_out, int out_size) {
    const float* inputs = (const float*)d_in[0];
    // d_in[1] = state (unused by forward)
    const float* weight = (const float*)d_in[2];
    const float* biases = (const float*)d_in[3];
    const float* vals0  = (const float*)d_in[4];
    const float* vals1  = (const float*)d_in[5];
    const int*   rows0  = (const int*)d_in[6];
    const int*   cols0  = (const int*)d_in[7];
    const int*   rows1  = (const int*)d_in[8];
    const int*   cols1  = (const int*)d_in[9];
    int E = in_sizes[4];

    cudaFuncSetAttribute(k_gemm_tc, cudaFuncAttributeMaxDynamicSharedMemorySize, GEMM_SMEM);

    int eb = (E + 255) / 256;
    dim3 eg(eb, 2);

    // Order: hist(0) scan(1) fill(2) gemm(3) spmm... — ncu capture (launch
    // index 3 empirically) lands on k_gemm_tc this round.
    // g_cnt is zero at module load; k_spmm_cheb(doZero=1) re-zeros it each
    // replay AFTER k_fill2 is done with the counters.
    k_hist2<<<eg, 256>>>(rows0, rows1, E);
    k_scan<<<2, 1024>>>();
    k_fill2<<<eg, 256>>>(rows0, cols0, vals0, rows1, cols1, vals1, E);

    k_gemm_tc<<<NN / NPB, 256, GEMM_SMEM>>>(inputs, weight, biases);

    // out = P + A0*(Y1 + 2*A0*Y2) + A1*(Y3 + 2*A1*Y4)
    dim3 sg(NN, 4);
    k_spmm_cheb<<<sg, 128>>>(0, 1, 0, 1);          // g_H0 <- Y1 + 2*A0*Y2  (=T0), zero cnt
    k_spmm_cheb<<<sg, 128>>>(1, 3, 2, 0);          // g_H2 <- Y3 + 2*A1*Y4  (=T1)
    k_final<<<sg, 128>>>((float*)d_out);           // out = P + A0*T0 + A1*T1
}

// round 13
// speedup vs baseline: 1.4817x; 1.4817x over previous
#include <cuda_runtime.h>
#include <cuda_fp16.h>
#include <cstdint>

// ---------------- problem constants ----------------
#define NN 10000            // nodes
#define BB 64               // batch
#define DD 66               // input feature dim
#define OO 64               // output dim
#define UU 320              // 5 * OO
#define FF 4096             // BB * OO  (spmm feature width, node-major)
#define EMAX 200000
#define NFSZ ((size_t)NN * FF)

#define KP 80               // padded K (5 k-tiles of 16)
#define SA 88               // As row stride in halfs (conflict-free frag loads)
#define SU 320              // Ws row stride in halfs
#define NPB 8               // nodes per gemm block
#define GEMM_SMEM (KP * SU * 2 + BB * SA * 2)   // 51200 + 11264 = 62464 B

// ---------------- device scratch (static: no allocs allowed) ----------------
__device__ float  g_P[NFSZ];            // P (then S) fp32
__device__ __half g_H[4][NFSZ];         // Y1..Y4 fp16; T0 overwrites Y1, T1 overwrites Y3
__device__ int    g_rp[2][NN + 1];
__device__ int    g_cnt[2][NN];         // zero at load; re-zeroed each replay in 1st spmm
__device__ int    g_cur[2][NN];
__device__ int    g_ecols[2][EMAX];
__device__ float  g_evals[2][EMAX];

// ---------------- CSR build ----------------
__global__ void k_hist2(const int* __restrict__ rows0, const int* __restrict__ rows1,
                        int E) {
    int e = blockIdx.x * blockDim.x + threadIdx.x;
    int sup = blockIdx.y;
    const int* rows = sup ? rows1 : rows0;
    if (e < E) atomicAdd(&g_cnt[sup][rows[e]], 1);
}

__global__ void k_scan() {
    __shared__ int ssum[1024];
    int sup = blockIdx.x;
    const int* cnt = g_cnt[sup];
    int* rp  = g_rp[sup];
    int* cur = g_cur[sup];
    int t = threadIdx.x;
    int base = t * 10;
    int local[10];
    int sum = 0;
#pragma unroll
    for (int k = 0; k < 10; k++) {
        int i = base + k;
        int v = (i < NN) ? cnt[i] : 0;
        local[k] = sum;
        sum += v;
    }
    ssum[t] = sum;
    __syncthreads();
    for (int off = 1; off < 1024; off <<= 1) {
        int v = (t >= off) ? ssum[t - off] : 0;
        __syncthreads();
        ssum[t] += v;
        __syncthreads();
    }
    int prev = (t > 0) ? ssum[t - 1] : 0;
#pragma unroll
    for (int k = 0; k < 10; k++) {
        int i = base + k;
        if (i < NN) {
            int v = prev + local[k];
            rp[i]  = v;
            cur[i] = v;
        }
    }
    if (t == 1023) rp[NN] = ssum[1023];
}

__global__ void k_fill2(const int* __restrict__ rows0, const int* __restrict__ cols0,
                        const float* __restrict__ vals0,
                        const int* __restrict__ rows1, const int* __restrict__ cols1,
                        const float* __restrict__ vals1, int E) {
    int e = blockIdx.x * blockDim.x + threadIdx.x;
    int sup = blockIdx.y;
    const int*   rows = sup ? rows1 : rows0;
    const int*   cols = sup ? cols1 : cols0;
    const float* vals = sup ? vals1 : vals0;
    if (e < E) {
        int r = rows[e];
        int pos = atomicAdd(&g_cur[sup][r], 1);
        g_ecols[sup][pos] = cols[e];
        g_evals[sup][pos] = vals[e];
    }
}

// ---------------- tensor-core GEMM0 --------------------------------------
// P = x0(W0-W2-W4)+bias (fp32), Ym = x0 Wm (fp16), via mma.sync m16n8k16.
// R12 fixes vs R10 version: kt-outer/j-inner (5 independent acc chains),
// no a[] prefetch array (regs < 128, no spills), register-prefetch x staging
// pipeline (LDG of node it+1 overlapped with compute of node it).
__device__ __forceinline__ void mma16816(float& c0, float& c1, float& c2, float& c3,
                                         uint32_t a0, uint32_t a1, uint32_t a2,
                                         uint32_t a3, uint32_t b0, uint32_t b1) {
    asm volatile(
        "mma.sync.aligned.m16n8k16.row.col.f32.f16.f16.f32 "
        "{%0,%1,%2,%3}, {%4,%5,%6,%7}, {%8,%9}, {%0,%1,%2,%3};\n"
        : "+f"(c0), "+f"(c1), "+f"(c2), "+f"(c3)
        : "r"(a0), "r"(a1), "r"(a2), "r"(a3), "r"(b0), "r"(b1));
}

__global__ void __launch_bounds__(256, 2)
k_gemm_tc(const float* __restrict__ x, const float* __restrict__ W,
          const float* __restrict__ bias) {
    extern __shared__ char smem[];
    __half* Ws = (__half*)smem;                    // [KP][SU]  folded weights fp16
    __half* As = (__half*)(smem + KP * SU * 2);    // [BB][SA]  one node fp16
    const uint32_t* As32 = (const uint32_t*)As;

    int tid  = threadIdx.x;
    int w    = tid >> 5;
    int lane = tid & 31;
    int qr   = lane >> 2;      // t/4
    int qc   = lane & 3;       // t%4

    // ---- stage folded weights ----
    for (int idx = tid; idx < KP * UU; idx += 256) {
        int d = idx / UU;
        int u = idx - d * UU;
        float v;
        if (d >= DD) v = 0.f;
        else if (u < 64)
            v = __ldg(&W[d * 320 + u]) - __ldg(&W[d * 320 + 128 + u])
              - __ldg(&W[d * 320 + 256 + u]);
        else
            v = __ldg(&W[d * 320 + u]);
        Ws[d * SU + u] = __float2half_rn(v);
    }
    __syncthreads();

    // ---- B fragments into registers (node-invariant, 50 regs) ----
    uint32_t Breg[5][5][2];
#pragma unroll
    for (int j = 0; j < 5; j++) {
        int u = j * 64 + w * 8 + qr;
#pragma unroll
        for (int kt = 0; kt < 5; kt++) {
            int k0 = kt * 16 + qc * 2;
            __half2 p0 = __halves2half2(Ws[k0 * SU + u], Ws[(k0 + 1) * SU + u]);
            __half2 p1 = __halves2half2(Ws[(k0 + 8) * SU + u], Ws[(k0 + 9) * SU + u]);
            Breg[j][kt][0] = *(uint32_t*)&p0;
            Breg[j][kt][1] = *(uint32_t*)&p1;
        }
    }

    int oC = w * 8 + qc * 2;
    float bias0 = __ldg(&bias[oC]);
    float bias1 = __ldg(&bias[oC + 1]);

    // ---- x staging pipeline: prefetch node 0 into registers ----
    // idx = tid + 256*i -> b = idx/40, d2 = idx%40; pair (d=2*d2, d+1).
    // d2 <= 32 covers d = 0..65 exactly (DD=66); d2 >= 33 is zero padding.
    float2 pf[10];
    {
        int n0 = blockIdx.x * NPB;
#pragma unroll
        for (int i = 0; i < 10; i++) {
            int idx = tid + 256 * i;
            int b = idx / 40, d2 = idx - b * 40;
            pf[i] = (d2 <= 32)
                ? *(const float2*)&x[(size_t)b * ((size_t)NN * DD) + (size_t)n0 * DD + d2 * 2]
                : make_float2(0.f, 0.f);
        }
    }

    for (int it = 0; it < NPB; it++) {
        __syncthreads();   // previous node's As consumers done
#pragma unroll
        for (int i = 0; i < 10; i++) {
            int idx = tid + 256 * i;
            int b = idx / 40, d2 = idx - b * 40;
            ((__half2*)As)[b * (SA / 2) + d2] = __floats2half2_rn(pf[i].x, pf[i].y);
        }
        if (it + 1 < NPB) {     // issue next node's LDGs; consumed next iter
            int n1 = blockIdx.x * NPB + it + 1;
#pragma unroll
            for (int i = 0; i < 10; i++) {
                int idx = tid + 256 * i;
                int b = idx / 40, d2 = idx - b * 40;
                pf[i] = (d2 <= 32)
                    ? *(const float2*)&x[(size_t)b * ((size_t)NN * DD) + (size_t)n1 * DD + d2 * 2]
                    : make_float2(0.f, 0.f);
            }
        }
        __syncthreads();   // As ready

        int n = blockIdx.x * NPB + it;
#pragma unroll
        for (int m = 0; m < 4; m++) {
            float c[5][4];
#pragma unroll
            for (int j = 0; j < 5; j++)
#pragma unroll
                for (int q = 0; q < 4; q++)
                    c[j][q] = 0.f;

            int r = m * 16 + qr;
#pragma unroll
            for (int kt = 0; kt < 5; kt++) {
                uint32_t a0 = As32[r * (SA / 2) + kt * 8 + qc];
                uint32_t a1 = As32[(r + 8) * (SA / 2) + kt * 8 + qc];
                uint32_t a2 = As32[r * (SA / 2) + kt * 8 + qc + 4];
                uint32_t a3 = As32[(r + 8) * (SA / 2) + kt * 8 + qc + 4];
#pragma unroll
                for (int j = 0; j < 5; j++)      // 5 independent acc chains
                    mma16816(c[j][0], c[j][1], c[j][2], c[j][3],
                             a0, a1, a2, a3, Breg[j][kt][0], Breg[j][kt][1]);
            }

            int bLo = m * 16 + qr;
            int bHi = bLo + 8;
            {
                float* dst = g_P + (size_t)n * FF;
                *(float2*)&dst[bLo * 64 + oC] = make_float2(c[0][0] + bias0, c[0][1] + bias1);
                *(float2*)&dst[bHi * 64 + oC] = make_float2(c[0][2] + bias0, c[0][3] + bias1);
            }
#pragma unroll
            for (int j = 1; j < 5; j++) {
                __half* dst = g_H[j - 1] + (size_t)n * FF;
                *(__half2*)&dst[bLo * 64 + oC] = __floats2half2_rn(c[j][0], c[j][1]);
                *(__half2*)&dst[bHi * 64 + oC] = __floats2half2_rn(c[j][2], c[j][3]);
            }
        }
    }
}

// ---------------- SpMM (CSR gather, fp16 sources) — R10 4-pass structure ---
// MODE 0: T = aux(h) + 2*A*src(h)   -> fp16, in-place into aux buffer
// MODE 1: S = P(f32) +   A*src(h)   -> fp32, in-place into g_P
// MODE 2: out = S(f32) + A*src(h)   -> d_out fp32, transposed to [B, N*O]
// grid = (NN, 4 chunks); chunk slow -> 20 MB gather slice stays L2-resident.
template <int MODE>
__global__ void __launch_bounds__(128)
k_spmm(int sup, int srcIdx, int auxIdx, float* __restrict__ dout, int doZero) {
    int r  = blockIdx.x;
    int fq = blockIdx.y * 128 + threadIdx.x;     // uint4 index within row (512/row)

    if (doZero && blockIdx.y == 0) {             // re-zero counters for next replay
        int gi = r * 128 + threadIdx.x;
        if (gi < 2 * NN) ((int*)g_cnt)[gi] = 0;
    }

    const int*   rp   = g_rp[sup];
    const int*   cols = g_ecols[sup];
    const float* vals = g_evals[sup];
    const uint4* src  = (const uint4*)(g_H[srcIdx]);

    int s = __ldg(&rp[r]);
    int e = __ldg(&rp[r + 1]);

    float a0 = 0.f, a1 = 0.f, a2 = 0.f, a3 = 0.f;
    float a4 = 0.f, a5 = 0.f, a6 = 0.f, a7 = 0.f;

    for (int i = s; i < e; i += 8) {
        int   cc[8];
        float vv[8];
#pragma unroll
        for (int j = 0; j < 8; j++) {
            int idx = i + j;
            bool ok = idx < e;
            cc[j] = ok ? __ldg(&cols[idx]) : 0;
            vv[j] = ok ? __ldg(&vals[idx]) : 0.f;
        }
#pragma unroll
        for (int j = 0; j < 8; j++) {
            uint4 q = __ldg(&src[(size_t)cc[j] * 512 + fq]);
            const __half2* hp = (const __half2*)&q;
            float2 f0v = __half22float2(hp[0]);
            float2 f1v = __half22float2(hp[1]);
            float2 f2v = __half22float2(hp[2]);
            float2 f3v = __half22float2(hp[3]);
            float v = vv[j];
            a0 = fmaf(v, f0v.x, a0); a1 = fmaf(v, f0v.y, a1);
            a2 = fmaf(v, f1v.x, a2); a3 = fmaf(v, f1v.y, a3);
            a4 = fmaf(v, f2v.x, a4); a5 = fmaf(v, f2v.y, a5);
            a6 = fmaf(v, f3v.x, a6); a7 = fmaf(v, f3v.y, a7);
        }
    }

    if (MODE == 0) {
        uint4* aux = (uint4*)(g_H[auxIdx]);
        uint4 qa = __ldg((const uint4*)&aux[(size_t)r * 512 + fq]);
        const __half2* hp = (const __half2*)&qa;
        float2 b0 = __half22float2(hp[0]);
        float2 b1 = __half22float2(hp[1]);
        float2 b2 = __half22float2(hp[2]);
        float2 b3 = __half22float2(hp[3]);
        __half2 h[4];
        h[0] = __floats2half2_rn(b0.x + 2.f * a0, b0.y + 2.f * a1);
        h[1] = __floats2half2_rn(b1.x + 2.f * a2, b1.y + 2.f * a3);
        h[2] = __floats2half2_rn(b2.x + 2.f * a4, b2.y + 2.f * a5);
        h[3] = __floats2half2_rn(b3.x + 2.f * a6, b3.y + 2.f * a7);
        aux[(size_t)r * 512 + fq] = *(uint4*)h;
    } else {
        const float4* auxP = (const float4*)g_P;
        float4 p0 = __ldg(&auxP[(size_t)r * 1024 + fq * 2]);
        float4 p1 = __ldg(&auxP[(size_t)r * 1024 + fq * 2 + 1]);
        float4 r0 = make_float4(p0.x + a0, p0.y + a1, p0.z + a2, p0.w + a3);
        float4 r1 = make_float4(p1.x + a4, p1.y + a5, p1.z + a6, p1.w + a7);
        if (MODE == 1) {
            float4* outP = (float4*)g_P;
            outP[(size_t)r * 1024 + fq * 2]     = r0;
            outP[(size_t)r * 1024 + fq * 2 + 1] = r1;
        } else {
            int f0 = fq * 8;
            int b  = f0 >> 6;
            int o  = f0 & 63;
            float4* od = (float4*)dout;
            size_t base = (size_t)b * ((size_t)NN * 16) + (size_t)r * 16 + (o >> 2);
            od[base]     = r0;
            od[base + 1] = r1;
        }
    }
}

// ---------------- launch ----------------
extern "C" void kernel_launch(void* const* d_in, const int* in_sizes, int n_in,
                              void* d_out, int out_size) {
    const float* inputs = (const float*)d_in[0];
    // d_in[1] = state (unused by forward)
    const float* weight = (const float*)d_in[2];
    const float* biases = (const float*)d_in[3];
    const float* vals0  = (const float*)d_in[4];
    const float* vals1  = (const float*)d_in[5];
    const int*   rows0  = (const int*)d_in[6];
    const int*   cols0  = (const int*)d_in[7];
    const int*   rows1  = (const int*)d_in[8];
    const int*   cols1  = (const int*)d_in[9];
    int E = in_sizes[4];

    cudaFuncSetAttribute(k_gemm_tc, cudaFuncAttributeMaxDynamicSharedMemorySize, GEMM_SMEM);

    int eb = (E + 255) / 256;
    dim3 eg(eb, 2);

    // Order: hist(0) scan(1) fill(2) gemm(3) spmm(4..7) — ncu capture lands
    // on the reworked k_gemm_tc. g_cnt zero at load; first spmm re-zeros it
    // for the next replay (after k_fill2 is done with the counters).
    k_hist2<<<eg, 256>>>(rows0, rows1, E);
    k_scan<<<2, 1024>>>();
    k_fill2<<<eg, 256>>>(rows0, cols0, vals0, rows1, cols1, vals1, E);

    k_gemm_tc<<<NN / NPB, 256, GEMM_SMEM>>>(inputs, weight, biases);

    // out = P + A0*(Y1 + 2*A0*Y2) + A1*(Y3 + 2*A1*Y4)  — R10 4-pass structure
    dim3 sg(NN, 4);
    k_spmm<0><<<sg, 128>>>(0, 1, 0, nullptr, 1);       // g_H0 <- Y1 + 2*A0*Y2  (=T0)
    k_spmm<1><<<sg, 128>>>(0, 0, 0, nullptr, 0);       // g_P  <- P + A0*T0     (=S)
    k_spmm<0><<<sg, 128>>>(1, 3, 2, nullptr, 0);       // g_H2 <- Y3 + 2*A1*Y4  (=T1)
    k_spmm<2><<<sg, 128>>>(1, 2, 0, (float*)d_out, 0); // out  = S + A1*T1 (transposed)
}